// round 1
// baseline (speedup 1.0000x reference)
#include <cuda_runtime.h>
#include <cstdint>

// Problem constants
#define NB   4      // batch
#define H    512    // projection height
#define W    360    // number of angles
#define D    512    // output image side

// Scratch: filtered sinogram in [w][y][n] layout (float4 per (w,y)) = 2.95 MB
__device__ float4 g_filt[W * H];

// ---------------------------------------------------------------------------
// Kernel A: circular ramp filtering.
//   filt[i, w, n] = sum_k radon[n, (i + k + 257) & 511, w] * hG[k]
// j-broadcast formulation: for each source row j (broadcast float4 across the
// CTA), each thread adds r[j] * hG[(j - i - 257) & 511] into its rows.
// One CTA per angle w; 128 threads, 4 rows each (i = tid + 128*m).
// Final scale pi/(2W) folded in here.
// ---------------------------------------------------------------------------
__global__ __launch_bounds__(128) void filter_kernel(
    const float* __restrict__ radon,  // [NB][H][W]
    const float* __restrict__ hG)     // [H]
{
    const int w   = blockIdx.x;
    const int tid = threadIdx.x;

    __shared__ float4 r_s[H];   // r_s[y] = radon column, 4 batches packed
    __shared__ float  h_s[H];

    // Load the 4-batch column for this angle (scattered gmem, tiny volume)
    for (int idx = tid; idx < H * NB; idx += 128) {
        const int y = idx >> 2;
        const int n = idx & 3;
        reinterpret_cast<float*>(r_s)[idx] = radon[(n * H + y) * W + w];
    }
    for (int k = tid; k < H; k += 128) h_s[k] = hG[k];
    __syncthreads();

    float4 acc[4];
#pragma unroll
    for (int m = 0; m < 4; m++) acc[m] = make_float4(0.f, 0.f, 0.f, 0.f);

#pragma unroll 2
    for (int j = 0; j < H; j++) {
        const float4 r = r_s[j];          // broadcast across warp
#pragma unroll
        for (int m = 0; m < 4; m++) {
            const int i = tid + (m << 7);
            const float h = h_s[(j - i - 257) & (H - 1)];  // conflict-free
            acc[m].x = fmaf(r.x, h, acc[m].x);
            acc[m].y = fmaf(r.y, h, acc[m].y);
            acc[m].z = fmaf(r.z, h, acc[m].z);
            acc[m].w = fmaf(r.w, h, acc[m].w);
        }
    }

    const float scale = 0.004363323129985824f;  // pi / (2*W)
#pragma unroll
    for (int m = 0; m < 4; m++) {
        const int y = tid + (m << 7);
        float4 v = acc[m];
        v.x *= scale; v.y *= scale; v.z *= scale; v.w *= scale;
        g_filt[w * H + y] = v;   // coalesced float4 stores
    }
}

// ---------------------------------------------------------------------------
// cp.async helpers (16B, L2-only)
// ---------------------------------------------------------------------------
static __device__ __forceinline__ void cp_async16(void* smem, const void* gmem) {
    const uint32_t s = (uint32_t)__cvta_generic_to_shared(smem);
    asm volatile("cp.async.cg.shared.global [%0], [%1], 16;\n" :: "r"(s), "l"(gmem));
}
static __device__ __forceinline__ void cp_commit() {
    asm volatile("cp.async.commit_group;\n");
}
template <int N>
static __device__ __forceinline__ void cp_wait() {
    asm volatile("cp.async.wait_group %0;\n" :: "n"(N));
}

// ---------------------------------------------------------------------------
// Kernel B: backprojection with analytic t_y.
//   py(i,j,w) = (j-256)*cos(th)*511/512 - (i-256)*sin(th)*511/512 + 255.5
//   out[n,i,j] = sum_w bilinear(filt[w, :, n], py)   (zero weight outside [0,H))
// Grid: 128 CTAs = 16 j-tiles x 8 i-tiles; tile = 32(j) x 64(i).
// Block 256 = (32 tx along j) x (8 ty); each thread owns 8 i-pixels (stride 8)
// and all 4 batches (float4), accumulating 32 floats in registers.
// Angle columns staged to smem with cp.async double buffering.
// ---------------------------------------------------------------------------
__global__ __launch_bounds__(256) void backproj_kernel(float* __restrict__ out)
{
    __shared__ float4 buf[2][H];    // 2 x 8KB
    __shared__ float  cs[W], ss[W];

    const int tid = threadIdx.x;
    const int tx  = tid & 31;        // j within tile
    const int ty  = tid >> 5;        // 0..7
    const int jt  = blockIdx.x & 15;
    const int it  = blockIdx.x >> 4;

    const int j     = jt * 32 + tx;
    const int ibase = it * 64 + ty;

    // Per-angle constants: cos/sin(pi * w/360) * (511/512), fp64 for accuracy
    for (int a = tid; a < W; a += 256) {
        double s, c;
        sincospi((double)a / 360.0, &s, &c);
        cs[a] = (float)(c * (511.0 / 512.0));
        ss[a] = (float)(s * (511.0 / 512.0));
    }

    const float fj = (float)(j - 256);
    float fi[8];
#pragma unroll
    for (int p = 0; p < 8; p++) fi[p] = (float)(ibase + 8 * p - 256);

    float4 acc[8];
#pragma unroll
    for (int p = 0; p < 8; p++) acc[p] = make_float4(0.f, 0.f, 0.f, 0.f);

    // Prefetch angle 0
    {
        const float4* src = &g_filt[0];
#pragma unroll
        for (int q = 0; q < 2; q++) {
            const int e = tid + 256 * q;
            cp_async16(&buf[0][e], &src[e]);
        }
        cp_commit();
    }

    for (int w = 0; w < W; w++) {
        if (w + 1 < W) {
            const float4* src = &g_filt[(w + 1) * H];
            float4* dst = buf[(w + 1) & 1];
#pragma unroll
            for (int q = 0; q < 2; q++) {
                const int e = tid + 256 * q;
                cp_async16(&dst[e], &src[e]);
            }
            cp_commit();
            cp_wait<1>();
        } else {
            cp_wait<0>();
        }
        __syncthreads();   // staged column + (first iter) cs/ss visible

        const float  C = cs[w];
        const float  S = ss[w];
        const float4* b = buf[w & 1];

#pragma unroll
        for (int p = 0; p < 8; p++) {
            const float py = fmaf(fj, C, fmaf(-fi[p], S, 255.5f));
            const float yf = floorf(py);
            const float fy = py - yf;
            const int   y0 = (int)yf;

            const float w0 = (y0 >= 0  && y0 < H)     ? (1.0f - fy) : 0.0f;
            const float w1 = (y0 >= -1 && y0 < H - 1) ? fy          : 0.0f;
            const int   i0 = min(max(y0, 0), H - 1);
            const int   i1 = min(max(y0 + 1, 0), H - 1);

            const float4 v0 = b[i0];
            const float4 v1 = b[i1];
            acc[p].x = fmaf(v0.x, w0, fmaf(v1.x, w1, acc[p].x));
            acc[p].y = fmaf(v0.y, w0, fmaf(v1.y, w1, acc[p].y));
            acc[p].z = fmaf(v0.z, w0, fmaf(v1.z, w1, acc[p].z));
            acc[p].w = fmaf(v0.w, w0, fmaf(v1.w, w1, acc[p].w));
        }
        __syncthreads();   // done reading buf[w&1] before it is overwritten
    }

    // Store: out[n][0][i][j], contiguous in j -> coalesced
#pragma unroll
    for (int p = 0; p < 8; p++) {
        const int i    = ibase + 8 * p;
        const int base = i * D + j;
        out[0 * D * D + base] = acc[p].x;
        out[1 * D * D + base] = acc[p].y;
        out[2 * D * D + base] = acc[p].z;
        out[3 * D * D + base] = acc[p].w;
    }
}

// ---------------------------------------------------------------------------
extern "C" void kernel_launch(void* const* d_in, const int* in_sizes, int n_in,
                              void* d_out, int out_size)
{
    // Identify inputs by element count (robust to ordering):
    //   radon: 4*512*360 = 737280, hG: 512, t_y: 94371840 (unused!)
    const float* radon = nullptr;
    const float* hG    = nullptr;
    for (int i = 0; i < n_in; i++) {
        if (in_sizes[i] == NB * H * W) radon = (const float*)d_in[i];
        else if (in_sizes[i] == H)     hG    = (const float*)d_in[i];
    }
    if (!radon) radon = (const float*)d_in[0];
    if (!hG)    hG    = (const float*)d_in[1];

    float* out = (float*)d_out;

    filter_kernel<<<W, 128>>>(radon, hG);
    backproj_kernel<<<128, 256>>>(out);
}

// round 2
// speedup vs baseline: 1.1569x; 1.1569x over previous
#include <cuda_runtime.h>
#include <cstdint>

#define NB   4      // batch
#define H    512    // projection height
#define W    360    // number of angles
#define D    512    // output image side
#define NW   180    // angles per backproj half

typedef unsigned long long u64;

// Scratch: filtered sinogram in [w][y][n4] layout (float4 per (w,y)) = 2.95 MB
__device__ float4 g_filt[W * H];
// Partial image from angle-half 1
__device__ float g_part[NB * D * D];

// ---------------------------------------------------------------------------
// Packed f32x2 helpers
// ---------------------------------------------------------------------------
static __device__ __forceinline__ u64 pack2(float a, float b) {
    u64 r;
    asm("mov.b64 %0, {%1, %2};" : "=l"(r)
        : "r"(__float_as_uint(a)), "r"(__float_as_uint(b)));
    return r;
}
static __device__ __forceinline__ void fma2(u64& d, u64 a, u64 b) {
    asm("fma.rn.f32x2 %0, %1, %2, %3;" : "=l"(d) : "l"(a), "l"(b), "l"(d));
}
static __device__ __forceinline__ float2 unpack2(u64 v) {
    unsigned lo, hi;
    asm("mov.b64 {%0, %1}, %2;" : "=r"(lo), "=r"(hi) : "l"(v));
    return make_float2(__uint_as_float(lo), __uint_as_float(hi));
}

// ---------------------------------------------------------------------------
// cp.async helpers (16B)
// ---------------------------------------------------------------------------
static __device__ __forceinline__ void cp_async16(void* smem, const void* gmem) {
    const uint32_t s = (uint32_t)__cvta_generic_to_shared(smem);
    asm volatile("cp.async.cg.shared.global [%0], [%1], 16;\n" :: "r"(s), "l"(gmem));
}
static __device__ __forceinline__ void cp_commit() {
    asm volatile("cp.async.commit_group;\n");
}
template <int N>
static __device__ __forceinline__ void cp_wait() {
    asm volatile("cp.async.wait_group %0;\n" :: "n"(N));
}

// ---------------------------------------------------------------------------
// Kernel A: circular ramp filtering (validated indexing from round 1):
//   filt[i, w, n] = sum_j radon[n, j, w] * hG[(j - i - 257) & 511]
// 360 CTAs x 256 threads; each thread owns rows i = tid, tid+256.
// Packed f32x2 FMA; h table pre-duplicated as (h,h) u64.
// Scale pi/(2W) folded in.
// ---------------------------------------------------------------------------
__global__ __launch_bounds__(256) void filter_kernel(
    const float* __restrict__ radon,  // [NB][H][W]
    const float* __restrict__ hG)     // [H]
{
    const int w   = blockIdx.x;
    const int tid = threadIdx.x;

    __shared__ float4 r_s[H];   // 4-batch column
    __shared__ u64    h2[H];    // (h, h)

    for (int idx = tid; idx < H * NB; idx += 256) {
        const int y = idx >> 2;
        const int n = idx & 3;
        reinterpret_cast<float*>(r_s)[idx] = radon[(n * H + y) * W + w];
    }
    for (int k = tid; k < H; k += 256) {
        const float h = hG[k];
        h2[k] = pack2(h, h);
    }
    __syncthreads();

    u64 a01[2] = {0ull, 0ull};   // batches 0,1 for rows i0, i1
    u64 a23[2] = {0ull, 0ull};   // batches 2,3
    const int i0 = tid;
    const int i1 = tid + 256;

#pragma unroll 4
    for (int j = 0; j < H; j++) {
        const float4 r = r_s[j];
        const u64 rxy = pack2(r.x, r.y);
        const u64 rzw = pack2(r.z, r.w);
        const u64 hA  = h2[(j - i0 - 257) & (H - 1)];
        const u64 hB  = h2[(j - i1 - 257) & (H - 1)];
        fma2(a01[0], rxy, hA);
        fma2(a23[0], rzw, hA);
        fma2(a01[1], rxy, hB);
        fma2(a23[1], rzw, hB);
    }

    const float sc = 0.004363323129985824f;  // pi / (2*W)
#pragma unroll
    for (int m = 0; m < 2; m++) {
        const float2 p01 = unpack2(a01[m]);
        const float2 p23 = unpack2(a23[m]);
        const int y = tid + (m << 8);
        g_filt[w * H + y] = make_float4(p01.x * sc, p01.y * sc,
                                        p23.x * sc, p23.y * sc);
    }
}

// ---------------------------------------------------------------------------
// Kernel B: backprojection, analytic t_y, angle-split across 2 halves.
//   py(i,j,w) = (j-256)*cos(th)*511/512 - (i-256)*sin(th)*511/512 + 255.5
// Grid: 256 CTAs = 128 tiles (8 j-tiles x 16 i-tiles, tile 64j x 32i) x 2 halves.
// Block 512 = 64(tx:j) x 8(ty); each thread: 4 i-pixels (stride 8) x 4 batches.
// Triple-buffered cp.async staging, ONE __syncthreads per angle.
// Per-angle uniform interior fast path (no clamps); packed f32x2 accumulation.
// half 0 -> out, half 1 -> g_part.
// ---------------------------------------------------------------------------
__global__ __launch_bounds__(512, 2) void backproj_kernel(float* __restrict__ out)
{
    __shared__ ulonglong2 buf[3][H];   // 3 x 8KB
    __shared__ float cs[W], ss[W];

    const int tid  = threadIdx.x;
    const int tx   = tid & 63;        // j within tile
    const int ty   = tid >> 6;        // 0..7
    const int half = blockIdx.x & 1;
    const int tile = blockIdx.x >> 1; // 0..127
    const int jt   = tile & 7;        // 8 j-tiles of 64
    const int it   = tile >> 3;       // 16 i-tiles of 32

    const int j     = jt * 64 + tx;
    const int ibase = it * 32 + ty;   // i = ibase + 8*p, p<4

    for (int a = tid; a < W; a += 512) {
        double s, c;
        sincospi((double)a / 360.0, &s, &c);
        cs[a] = (float)(c * (511.0 / 512.0));
        ss[a] = (float)(s * (511.0 / 512.0));   // >= 0 for theta in [0, pi)
    }

    const float fj = (float)(j - 256);
    float fi[4];
#pragma unroll
    for (int p = 0; p < 4; p++) fi[p] = (float)(ibase + 8 * p - 256);

    // Tile corner coordinates for the per-angle interior test
    const float fj_lo = (float)(jt * 64 - 256);
    const float fj_hi = (float)(jt * 64 + 63 - 256);
    const float fi_lo = (float)(it * 32 - 256);
    const float fi_hi = (float)(it * 32 + 31 - 256);

    u64 a01[4] = {0ull, 0ull, 0ull, 0ull};
    u64 a23[4] = {0ull, 0ull, 0ull, 0ull};

    const int wbase = half * NW;
    const float4* fsrc = g_filt;

    // Prologue: stage angles wbase+0, wbase+1
    cp_async16(&buf[0][tid], &fsrc[(wbase + 0) * H + tid]);
    cp_commit();
    cp_async16(&buf[1][tid], &fsrc[(wbase + 1) * H + tid]);
    cp_commit();

    int cur = 0;
    for (int w = 0; w < NW; w++) {
        if (w + 2 < NW) cp_wait<1>(); else cp_wait<0>();
        __syncthreads();   // data visible to all; previous iter's reads done

        if (w + 2 < NW) {
            int tgt = cur + 2; if (tgt >= 3) tgt -= 3;
            cp_async16(&buf[tgt][tid], &fsrc[(wbase + w + 2) * H + tid]);
            cp_commit();
        }

        const int   aw = wbase + w;
        const float C  = cs[aw];
        const float S  = ss[aw];
        const ulonglong2* __restrict__ b = buf[cur];

        // Per-CTA-uniform interior test (S >= 0)
        const float pjmax = fmaxf(fj_lo * C, fj_hi * C);
        const float pjmin = fminf(fj_lo * C, fj_hi * C);
        const float pmax  = pjmax - fi_lo * S + 255.5f;
        const float pmin  = pjmin - fi_hi * S + 255.5f;

        if (pmin >= 0.5f && pmax <= 510.5f) {
            // Fast path: no clamps, truncation == floor
#pragma unroll
            for (int p = 0; p < 4; p++) {
                const float py = fmaf(fj, C, fmaf(-fi[p], S, 255.5f));
                const int   y0 = (int)py;
                const float fy = py - (float)y0;
                const ulonglong2 v0 = b[y0];
                const ulonglong2 v1 = b[y0 + 1];
                const u64 w0 = pack2(1.0f - fy, 1.0f - fy);
                const u64 w1 = pack2(fy, fy);
                fma2(a01[p], v0.x, w0);
                fma2(a23[p], v0.y, w0);
                fma2(a01[p], v1.x, w1);
                fma2(a23[p], v1.y, w1);
            }
        } else {
            // Slow path: full boundary handling (identical to reference)
#pragma unroll
            for (int p = 0; p < 4; p++) {
                const float py = fmaf(fj, C, fmaf(-fi[p], S, 255.5f));
                const float yf = floorf(py);
                const float fy = py - yf;
                const int   y0 = (int)yf;
                const float w0f = (y0 >= 0  && y0 < H)     ? (1.0f - fy) : 0.0f;
                const float w1f = (y0 >= -1 && y0 < H - 1) ? fy          : 0.0f;
                const int   c0 = min(max(y0, 0), H - 1);
                const int   c1 = min(max(y0 + 1, 0), H - 1);
                const ulonglong2 v0 = b[c0];
                const ulonglong2 v1 = b[c1];
                const u64 w0 = pack2(w0f, w0f);
                const u64 w1 = pack2(w1f, w1f);
                fma2(a01[p], v0.x, w0);
                fma2(a23[p], v0.y, w0);
                fma2(a01[p], v1.x, w1);
                fma2(a23[p], v1.y, w1);
            }
        }

        cur = (cur + 1 == 3) ? 0 : cur + 1;
    }

    float* __restrict__ dst = half ? g_part : out;
#pragma unroll
    for (int p = 0; p < 4; p++) {
        const int i    = ibase + 8 * p;
        const int base = i * D + j;
        const float2 b01 = unpack2(a01[p]);
        const float2 b23 = unpack2(a23[p]);
        dst[0 * D * D + base] = b01.x;
        dst[1 * D * D + base] = b01.y;
        dst[2 * D * D + base] = b23.x;
        dst[3 * D * D + base] = b23.y;
    }
}

// ---------------------------------------------------------------------------
// Kernel C: out += g_part (float4, grid-stride)
// ---------------------------------------------------------------------------
__global__ __launch_bounds__(256) void add_kernel(float* __restrict__ out)
{
    const int n4 = NB * D * D / 4;
    float4* o = reinterpret_cast<float4*>(out);
    const float4* p = reinterpret_cast<const float4*>(g_part);
    for (int k = blockIdx.x * 256 + threadIdx.x; k < n4; k += 256 * 256) {
        float4 a = o[k];
        const float4 b = p[k];
        a.x += b.x; a.y += b.y; a.z += b.z; a.w += b.w;
        o[k] = a;
    }
}

// ---------------------------------------------------------------------------
extern "C" void kernel_launch(void* const* d_in, const int* in_sizes, int n_in,
                              void* d_out, int out_size)
{
    const float* radon = nullptr;
    const float* hG    = nullptr;
    for (int i = 0; i < n_in; i++) {
        if (in_sizes[i] == NB * H * W) radon = (const float*)d_in[i];
        else if (in_sizes[i] == H)     hG    = (const float*)d_in[i];
    }
    if (!radon) radon = (const float*)d_in[0];
    if (!hG)    hG    = (const float*)d_in[1];

    float* out = (float*)d_out;

    filter_kernel<<<W, 256>>>(radon, hG);
    backproj_kernel<<<256, 512>>>(out);
    add_kernel<<<256, 256>>>(out);
}

// round 3
// speedup vs baseline: 1.3654x; 1.1802x over previous
#include <cuda_runtime.h>
#include <cstdint>

#define NB   4      // batch
#define H    512    // projection height
#define W    360    // number of angles
#define D    512    // output image side
#define NQ   90     // angles per backproj quarter
#define WIN  96     // staged window entries per angle (span <= 76 guaranteed)

typedef unsigned long long u64;

// Scratch: filtered sinogram in [w][y][n4] layout (float4 per (w,y)) = 2.95 MB
__device__ float4 g_filt[W * H];
// Partial images from angle-quarters 1..3
__device__ float g_part[3][NB * D * D];

// ---------------------------------------------------------------------------
// Packed f32x2 helpers
// ---------------------------------------------------------------------------
static __device__ __forceinline__ u64 pack2(float a, float b) {
    u64 r;
    asm("mov.b64 %0, {%1, %2};" : "=l"(r)
        : "r"(__float_as_uint(a)), "r"(__float_as_uint(b)));
    return r;
}
static __device__ __forceinline__ void fma2(u64& d, u64 a, u64 b) {
    asm("fma.rn.f32x2 %0, %1, %2, %3;" : "=l"(d) : "l"(a), "l"(b), "l"(d));
}
static __device__ __forceinline__ float2 unpack2(u64 v) {
    unsigned lo, hi;
    asm("mov.b64 {%0, %1}, %2;" : "=r"(lo), "=r"(hi) : "l"(v));
    return make_float2(__uint_as_float(lo), __uint_as_float(hi));
}

// ---------------------------------------------------------------------------
// cp.async helpers (16B)
// ---------------------------------------------------------------------------
static __device__ __forceinline__ void cp_async16(void* smem, const void* gmem) {
    const uint32_t s = (uint32_t)__cvta_generic_to_shared(smem);
    asm volatile("cp.async.cg.shared.global [%0], [%1], 16;\n" :: "r"(s), "l"(gmem));
}
static __device__ __forceinline__ void cp_commit() {
    asm volatile("cp.async.commit_group;\n");
}
template <int N>
static __device__ __forceinline__ void cp_wait() {
    asm volatile("cp.async.wait_group %0;\n" :: "n"(N));
}

// ---------------------------------------------------------------------------
// Kernel A: circular ramp filtering (round-1 proven version, ~26us):
//   filt[i, w, n] = sum_j radon[n, j, w] * hG[(j - i - 257) & 511]
// One CTA per angle; 128 threads, 4 rows each. Scale pi/(2W) folded in.
// ---------------------------------------------------------------------------
__global__ __launch_bounds__(128) void filter_kernel(
    const float* __restrict__ radon,  // [NB][H][W]
    const float* __restrict__ hG)     // [H]
{
    const int w   = blockIdx.x;
    const int tid = threadIdx.x;

    __shared__ float4 r_s[H];   // 4-batch column
    __shared__ float  h_s[H];

    for (int idx = tid; idx < H * NB; idx += 128) {
        const int y = idx >> 2;
        const int n = idx & 3;
        reinterpret_cast<float*>(r_s)[idx] = radon[(n * H + y) * W + w];
    }
    for (int k = tid; k < H; k += 128) h_s[k] = hG[k];
    __syncthreads();

    float4 acc[4];
#pragma unroll
    for (int m = 0; m < 4; m++) acc[m] = make_float4(0.f, 0.f, 0.f, 0.f);

#pragma unroll 2
    for (int j = 0; j < H; j++) {
        const float4 r = r_s[j];
#pragma unroll
        for (int m = 0; m < 4; m++) {
            const int i = tid + (m << 7);
            const float h = h_s[(j - i - 257) & (H - 1)];
            acc[m].x = fmaf(r.x, h, acc[m].x);
            acc[m].y = fmaf(r.y, h, acc[m].y);
            acc[m].z = fmaf(r.z, h, acc[m].z);
            acc[m].w = fmaf(r.w, h, acc[m].w);
        }
    }

    const float scale = 0.004363323129985824f;  // pi / (2*W)
#pragma unroll
    for (int m = 0; m < 4; m++) {
        const int y = tid + (m << 7);
        float4 v = acc[m];
        v.x *= scale; v.y *= scale; v.z *= scale; v.w *= scale;
        g_filt[w * H + y] = v;
    }
}

// ---------------------------------------------------------------------------
// Kernel B: backprojection, analytic t_y, angle-quarter split, WINDOW staging.
//   py(i,j,w) = (j-256)*cos(th)*511/512 - (i-256)*sin(th)*511/512 + 255.5
// A 64j x 32i tile only touches a <=76-entry y-window per angle, so we stage
// a 96-entry window (1.5KB) instead of the whole 8KB column. Smem drops to
// ~5.4KB/CTA -> occupancy 4 CTAs/SM, and CTA count becomes cheap:
// grid = 128 tiles x 4 quarters (90 angles each) = 512 CTAs x 256 threads.
// Block 256 = 64(tx:j) x 4(ty); each thread: 8 i-pixels (stride 4) x 4 batches
// packed (f32x2 accumulators). Triple-buffered cp.async, 1 sync per angle.
// quarter 0 -> out, quarters 1..3 -> g_part[q-1].
// ---------------------------------------------------------------------------
__global__ __launch_bounds__(256, 4) void backproj_kernel(float* __restrict__ out)
{
    __shared__ float4 win[3][WIN];   // 3 x 1.5KB window buffers
    __shared__ float  cs_s[NQ], ss_s[NQ];

    const int tid  = threadIdx.x;
    const int tx   = tid & 63;         // j within tile
    const int ty   = tid >> 6;         // 0..3
    const int q    = blockIdx.x & 3;   // angle quarter
    const int tile = blockIdx.x >> 2;  // 0..127
    const int jt   = tile & 7;         // 8 j-tiles of 64
    const int it   = tile >> 3;        // 16 i-tiles of 32

    const int j     = jt * 64 + tx;
    const int ibase = it * 32 + ty;    // i = ibase + 4*p, p<8

    // Per-angle constants for this quarter (fp64 for accuracy)
    for (int a = tid; a < NQ; a += 256) {
        double s, c;
        sincospi((double)(q * NQ + a) / 360.0, &s, &c);
        cs_s[a] = (float)(c * (511.0 / 512.0));
        ss_s[a] = (float)(s * (511.0 / 512.0));   // >= 0 on [0, pi)
    }
    __syncthreads();

    const float fj  = (float)(j - 256);
    const float fi0 = (float)(ibase - 256);

    // Tile corners for uniform window/interior tests
    const float fj_lo = (float)(jt * 64 - 256);
    const float fj_hi = (float)(jt * 64 + 63 - 256);
    const float fi_lo = (float)(it * 32 - 256);
    const float fi_hi = (float)(it * 32 + 31 - 256);

    u64 a01[8], a23[8];
#pragma unroll
    for (int p = 0; p < 8; p++) { a01[p] = 0ull; a23[p] = 0ull; }

    // Uniform window base for angle index wl (deterministic recompute)
    auto window_base = [&](int wl, float C, float S) -> int {
        const float pjlo = fj_lo * C, pjhi = fj_hi * C;
        const float pmin = fminf(pjlo, pjhi) - fi_hi * S + 255.5f;
        int b = (int)floorf(pmin) - 1;
        b = max(b, 0);
        b = min(b, H - WIN);
        return b;
    };

    auto stage = [&](int slot, int wl) {
        const float C = cs_s[wl], S = ss_s[wl];
        const int base = window_base(wl, C, S);
        if (tid < WIN)
            cp_async16(&win[slot][tid], &g_filt[(q * NQ + wl) * H + base + tid]);
        cp_commit();
    };

    // Prologue: stage angles 0, 1
    stage(0, 0);
    stage(1, 1);

    for (int wl = 0; wl < NQ; wl++) {
        if (wl + 2 < NQ) cp_wait<1>(); else cp_wait<0>();
        __syncthreads();               // window wl visible; prior reads done
        if (wl + 2 < NQ) {
            int slot2 = wl + 2; slot2 -= (slot2 >= 3) ? 3 : 0; slot2 -= (slot2 >= 3) ? 3 : 0;
            stage((wl + 2) % 3, wl + 2);
        }

        const float C = cs_s[wl];
        const float S = ss_s[wl];

        const float pjlo = fj_lo * C, pjhi = fj_hi * C;
        const float pjmin = fminf(pjlo, pjhi), pjmax = fmaxf(pjlo, pjhi);
        const float pmin = pjmin - fi_hi * S + 255.5f;
        const float pmax = pjmax - fi_lo * S + 255.5f;

        if (pmax < -1.0f || pmin > 512.0f) continue;   // tile fully outside

        int base = (int)floorf(pmin) - 1;
        base = max(base, 0);
        base = min(base, H - WIN);
        const float basef = (float)base;

        int slot = wl; slot -= (slot >= 3) ? 3 : 0;   // wl % 3 cheaply
        while (slot >= 3) slot -= 3;
        const ulonglong2* __restrict__ b =
            reinterpret_cast<const ulonglong2*>(win[wl % 3]);

        const float dS = 4.0f * S;
        float pyl = fmaf(fj, C, fmaf(-fi0, S, 255.5f - basef));

        if (pmin > 0.0f && pmax < 510.5f) {
            // Fast path: all taps in-range, truncation == floor
#pragma unroll
            for (int p = 0; p < 8; p++) {
                const int   y0 = (int)pyl;
                const float fy = pyl - (float)y0;
                const ulonglong2 v0 = b[y0];
                const ulonglong2 v1 = b[y0 + 1];
                const u64 w0 = pack2(1.0f - fy, 1.0f - fy);
                const u64 w1 = pack2(fy, fy);
                fma2(a01[p], v0.x, w0);
                fma2(a23[p], v0.y, w0);
                fma2(a01[p], v1.x, w1);
                fma2(a23[p], v1.y, w1);
                pyl -= dS;
            }
        } else {
            // Slow path: exact boundary handling (matches reference semantics)
#pragma unroll
            for (int p = 0; p < 8; p++) {
                const float yf = floorf(pyl);
                const float fy = pyl - yf;
                const int   y0a = (int)yf + base;     // absolute y0
                const float w0f = (y0a >= 0  && y0a < H)     ? (1.0f - fy) : 0.0f;
                const float w1f = (y0a >= -1 && y0a < H - 1) ? fy          : 0.0f;
                const int   c0 = min(max(y0a, 0), H - 1) - base;
                const int   c1 = min(max(y0a + 1, 0), H - 1) - base;
                const ulonglong2 v0 = b[c0];
                const ulonglong2 v1 = b[c1];
                const u64 w0 = pack2(w0f, w0f);
                const u64 w1 = pack2(w1f, w1f);
                fma2(a01[p], v0.x, w0);
                fma2(a23[p], v0.y, w0);
                fma2(a01[p], v1.x, w1);
                fma2(a23[p], v1.y, w1);
                pyl -= dS;
            }
        }
    }

    float* __restrict__ dst = (q == 0) ? out : g_part[q - 1];
#pragma unroll
    for (int p = 0; p < 8; p++) {
        const int i    = ibase + 4 * p;
        const int base = i * D + j;
        const float2 b01 = unpack2(a01[p]);
        const float2 b23 = unpack2(a23[p]);
        dst[0 * D * D + base] = b01.x;
        dst[1 * D * D + base] = b01.y;
        dst[2 * D * D + base] = b23.x;
        dst[3 * D * D + base] = b23.y;
    }
}

// ---------------------------------------------------------------------------
// Kernel C: out += part0 + part1 + part2 (float4, grid-stride)
// ---------------------------------------------------------------------------
__global__ __launch_bounds__(256) void add_kernel(float* __restrict__ out)
{
    const int n4 = NB * D * D / 4;
    float4* o = reinterpret_cast<float4*>(out);
    const float4* p0 = reinterpret_cast<const float4*>(g_part[0]);
    const float4* p1 = reinterpret_cast<const float4*>(g_part[1]);
    const float4* p2 = reinterpret_cast<const float4*>(g_part[2]);
    for (int k = blockIdx.x * 256 + threadIdx.x; k < n4; k += 256 * 256) {
        float4 a = o[k];
        const float4 x = p0[k], y = p1[k], z = p2[k];
        a.x += x.x + y.x + z.x;
        a.y += x.y + y.y + z.y;
        a.z += x.z + y.z + z.z;
        a.w += x.w + y.w + z.w;
        o[k] = a;
    }
}

// ---------------------------------------------------------------------------
extern "C" void kernel_launch(void* const* d_in, const int* in_sizes, int n_in,
                              void* d_out, int out_size)
{
    const float* radon = nullptr;
    const float* hG    = nullptr;
    for (int i = 0; i < n_in; i++) {
        if (in_sizes[i] == NB * H * W) radon = (const float*)d_in[i];
        else if (in_sizes[i] == H)     hG    = (const float*)d_in[i];
    }
    if (!radon) radon = (const float*)d_in[0];
    if (!hG)    hG    = (const float*)d_in[1];

    float* out = (float*)d_out;

    filter_kernel<<<W, 128>>>(radon, hG);
    backproj_kernel<<<512, 256>>>(out);
    add_kernel<<<256, 256>>>(out);
}